// round 1
// baseline (speedup 1.0000x reference)
#include <cuda_runtime.h>
#include <stdint.h>

// Shapes (fixed for this problem)
#define BZ 4
#define LL 1024
#define SS 8
#define KH 128
#define EE 512
#define PRIME 2147483647u

// ---------------- device scratch (static; no allocation) ----------------
__device__ unsigned int  g_sig[2 * BZ * LL * KH];   // [q|k][b][l][k]  4 MB
__device__ unsigned char g_cnt[BZ * LL * LL];       // match counts    4 MB
__device__ float         g_lut[129];                // exp(score(m))
__device__ int           g_is64;
__device__ float         g_WvT[EE * EE];            // Wv transposed
__device__ float         g_M[EE * EE];              // M2[e2][e1] = sum_o Wo[e2][o]*Wv[o][e1]
__device__ float         g_u[BZ * LL * EE];         // value @ M2^T     8 MB
__device__ float         g_usum[BZ * EE];           // column sums of u
__device__ float         g_cvec[EE];                // Wo@bv + bo
__device__ float         g_rowinv[BZ * LL];         // 1/softmax denom
__device__ int           g_nzc[BZ * LL];
__device__ int           g_nzi[BZ * LL * LL];       // sparse j indices (worst-case capacity)
__device__ float         g_nzw[BZ * LL * LL];       // lut[m]-lut[0]

// ---------------- init: dtype detection + score LUT ----------------
__global__ void init_kernel(const void* ha) {
    int t = threadIdx.x;
    if (t == 0) {
        // hash_a values are >= 1. If stored as int64 (little endian), every odd
        // 32-bit word is the zero high half. If int32, odd words are a[1],a[3],... != 0.
        const int* p = (const int*)ha;
        int is64 = 1;
        for (int i = 0; i < 16; i++)
            if (p[2 * i + 1] != 0) is64 = 0;
        g_is64 = is64;
    }
    if (t < 129) {
        float j = (float)t / 128.0f;
        float delta = 16.0f * (1.0f - j) / (1.0f + j);
        float s = expf(-0.3f * delta);
        g_lut[t] = expf(s);   // softmax numerator exp(score)
    }
}

// ---------------- MinHash sketches ----------------
// one block per (q|k, b, l) row; thread = hash slot
__global__ __launch_bounds__(128) void sketch_kernel(const void* tsq, const void* tsk,
                                                     const void* ha, const void* hb) {
    __shared__ long long ids[SS];
    int row = blockIdx.x;          // 0..8191 (first 4096 = q)
    int k = threadIdx.x;
    int is64 = g_is64;
    const void* ts = (row < BZ * LL) ? tsq : tsk;
    int r = row & (BZ * LL - 1);
    if (k < SS) {
        ids[k] = is64 ? ((const long long*)ts)[r * SS + k]
                      : (long long)((const int*)ts)[r * SS + k];
    }
    __syncthreads();

    unsigned int mn = 0xffffffffu;
    if (is64) {
        unsigned long long a = (unsigned long long)((const long long*)ha)[k];
        unsigned long long b = (unsigned long long)((const long long*)hb)[k];
        #pragma unroll
        for (int s = 0; s < SS; s++) {
            unsigned long long x = (unsigned long long)ids[s] * a + b;   // < 2^47
            unsigned long long t = (x >> 31) + (x & 0x7fffffffULL);
            t = (t >> 31) + (t & 0x7fffffffULL);
            if (t >= 0x7fffffffULL) t -= 0x7fffffffULL;
            unsigned int v = (unsigned int)t;
            if (v < mn) mn = v;
        }
    } else {
        // int32 end-to-end: multiply wraps mod 2^32, then floor-mod PRIME (numpy semantics)
        unsigned int a = (unsigned int)((const int*)ha)[k];
        unsigned int b = (unsigned int)((const int*)hb)[k];
        #pragma unroll
        for (int s = 0; s < SS; s++) {
            unsigned int xu = (unsigned int)((long long)ids[s]) * a + b;  // wrap
            int x = (int)xu;
            long long m = (long long)x % (long long)PRIME;
            if (m < 0) m += (long long)PRIME;
            unsigned int v = (unsigned int)m;
            if (v < mn) mn = v;
        }
    }
    g_sig[row * KH + k] = mn;
}

// ---------------- transpose Wv -> WvT ----------------
__global__ void transpose_kernel(const float* __restrict__ in) {
    __shared__ float t[32][33];
    int bx = blockIdx.x, by = blockIdx.y;
    int tx = threadIdx.x, ty = threadIdx.y;   // 32 x 8
    #pragma unroll
    for (int i = 0; i < 32; i += 8)
        t[ty + i][tx] = in[(by * 32 + ty + i) * EE + bx * 32 + tx];
    __syncthreads();
    #pragma unroll
    for (int i = 0; i < 32; i += 8)
        g_WvT[(bx * 32 + ty + i) * EE + by * 32 + tx] = t[tx][ty + i];
}

// ---------------- NT GEMM body: C[i][j] = sum_k A[i][k]*Bt[j][k] ----------------
// BM=128, BN=64, BK=16, 256 threads, 8x4 per thread
__device__ __forceinline__ void gemm_nt_body(const float* __restrict__ A,
                                             const float* __restrict__ Bt,
                                             float* __restrict__ C,
                                             int Kd, int Ndim) {
    __shared__ float As[16][132];
    __shared__ float Bs[16][68];
    int tid = threadIdx.x;
    int mi = tid & 15, ni = tid >> 4;
    int i0 = blockIdx.x * 128, j0 = blockIdx.y * 64;
    float acc[8][4] = {};
    for (int k0 = 0; k0 < Kd; k0 += 16) {
        #pragma unroll
        for (int t = 0; t < 2; t++) {
            int idx = tid + t * 256;
            int ar = idx >> 2, ac = idx & 3;
            float4 v = *(const float4*)&A[(i0 + ar) * Kd + k0 + ac * 4];
            As[ac * 4 + 0][ar] = v.x; As[ac * 4 + 1][ar] = v.y;
            As[ac * 4 + 2][ar] = v.z; As[ac * 4 + 3][ar] = v.w;
        }
        {
            int br = tid >> 2, bc = tid & 3;
            float4 v = *(const float4*)&Bt[(j0 + br) * Kd + k0 + bc * 4];
            Bs[bc * 4 + 0][br] = v.x; Bs[bc * 4 + 1][br] = v.y;
            Bs[bc * 4 + 2][br] = v.z; Bs[bc * 4 + 3][br] = v.w;
        }
        __syncthreads();
        #pragma unroll
        for (int k = 0; k < 16; k++) {
            float a[8], bb[4];
            #pragma unroll
            for (int r = 0; r < 8; r++) a[r] = As[k][mi * 8 + r];
            #pragma unroll
            for (int c = 0; c < 4; c++) bb[c] = Bs[k][ni * 4 + c];
            #pragma unroll
            for (int r = 0; r < 8; r++)
                #pragma unroll
                for (int c = 0; c < 4; c++)
                    acc[r][c] += a[r] * bb[c];
        }
        __syncthreads();
    }
    #pragma unroll
    for (int r = 0; r < 8; r++) {
        float4 o = make_float4(acc[r][0], acc[r][1], acc[r][2], acc[r][3]);
        *(float4*)&C[(i0 + mi * 8 + r) * Ndim + j0 + ni * 4] = o;
    }
}

__global__ __launch_bounds__(256) void gemm_M2_kernel(const float* __restrict__ Wo) {
    gemm_nt_body(Wo, g_WvT, g_M, EE, EE);           // M2[e2][e1]
}
__global__ __launch_bounds__(256) void gemm_u_kernel(const float* __restrict__ value) {
    gemm_nt_body(value, g_M, g_u, EE, EE);          // u[r][e2]
}

// ---------------- column sums of u ----------------
__global__ void usum_kernel() {
    int b = blockIdx.y;
    int e = blockIdx.x * 128 + threadIdx.x;
    const float* up = g_u + (size_t)b * LL * EE + e;
    float acc = 0.f;
    for (int r = 0; r < LL; r++) acc += up[r * EE];
    g_usum[b * EE + e] = acc;
}

// ---------------- c vector: Wo @ bv + bo ----------------
__global__ void cvec_kernel(const float* __restrict__ Wo,
                            const float* __restrict__ bv,
                            const float* __restrict__ bo) {
    int e2 = blockIdx.x * 128 + threadIdx.x;
    float acc = bo[e2];
    for (int e = 0; e < EE; e++) acc += Wo[e2 * EE + e] * bv[e];
    g_cvec[e2] = acc;
}

// ---------------- signature match counting (brute force, tiled) ----------------
// 64x64 pair tile per block, 256 threads, 4x4 per thread, k-chunks of 32
__global__ __launch_bounds__(256) void count_kernel() {
    __shared__ unsigned int sq[64][33];
    __shared__ unsigned int sk[64][33];
    int b = blockIdx.z;
    int q0 = blockIdx.x * 64, k0 = blockIdx.y * 64;
    int tid = threadIdx.x;
    int tx = tid & 15, ty = tid >> 4;
    const unsigned int* SQ = g_sig + (size_t)(b * LL) * KH;
    const unsigned int* SK = g_sig + (size_t)(BZ * LL + b * LL) * KH;
    unsigned int cnt[4][4] = {};
    for (int c0 = 0; c0 < KH; c0 += 32) {
        #pragma unroll
        for (int t = 0; t < 2; t++) {
            int idx = tid + t * 256;
            int r = idx >> 3, seg = idx & 7;
            uint4 v = *(const uint4*)&SQ[(q0 + r) * KH + c0 + seg * 4];
            sq[r][seg * 4 + 0] = v.x; sq[r][seg * 4 + 1] = v.y;
            sq[r][seg * 4 + 2] = v.z; sq[r][seg * 4 + 3] = v.w;
            uint4 w = *(const uint4*)&SK[(k0 + r) * KH + c0 + seg * 4];
            sk[r][seg * 4 + 0] = w.x; sk[r][seg * 4 + 1] = w.y;
            sk[r][seg * 4 + 2] = w.z; sk[r][seg * 4 + 3] = w.w;
        }
        __syncthreads();
        #pragma unroll
        for (int kk = 0; kk < 32; kk++) {
            unsigned int qa[4], kb[4];
            #pragma unroll
            for (int r = 0; r < 4; r++) qa[r] = sq[tx * 4 + r][kk];
            #pragma unroll
            for (int c = 0; c < 4; c++) kb[c] = sk[ty * 4 + c][kk];
            #pragma unroll
            for (int r = 0; r < 4; r++)
                #pragma unroll
                for (int c = 0; c < 4; c++)
                    cnt[r][c] += (qa[r] == kb[c]) ? 1u : 0u;
        }
        __syncthreads();
    }
    #pragma unroll
    for (int r = 0; r < 4; r++) {
        uchar4 o = make_uchar4((unsigned char)cnt[r][0], (unsigned char)cnt[r][1],
                               (unsigned char)cnt[r][2], (unsigned char)cnt[r][3]);
        *(uchar4*)&g_cnt[(size_t)(b * LL + q0 + tx * 4 + r) * LL + k0 + ty * 4] = o;
    }
}

// ---------------- build per-row sparse correction lists + softmax denom ----------------
// one warp per query row; deterministic ballot-compaction (ordered by j)
__global__ __launch_bounds__(256) void build_sparse_kernel() {
    int row = blockIdx.x * 8 + (threadIdx.x >> 5);
    int lane = threadIdx.x & 31;
    const unsigned char* cr = g_cnt + (size_t)row * LL;
    float lut0 = g_lut[0];
    float rsum = 0.f;
    int base = 0;
    int* oi = g_nzi + (size_t)row * LL;
    float* ow = g_nzw + (size_t)row * LL;
    for (int c = 0; c < 32; c++) {
        int j = c * 32 + lane;
        int m = cr[j];
        rsum += g_lut[m];
        unsigned mask = __ballot_sync(0xffffffffu, m != 0);
        if (m) {
            int pos = base + __popc(mask & ((1u << lane) - 1u));
            oi[pos] = j;
            ow[pos] = g_lut[m] - lut0;
        }
        base += __popc(mask);
    }
    #pragma unroll
    for (int o = 16; o; o >>= 1) rsum += __shfl_xor_sync(0xffffffffu, rsum, o);
    if (lane == 0) {
        g_nzc[row] = base;
        g_rowinv[row] = 1.0f / rsum;
    }
}

// ---------------- output: out = rowinv*(lut0*Usum + sum_t w_t*u[j_t]) + c ----------------
__global__ __launch_bounds__(128) void out_kernel(float* __restrict__ out) {
    int row = blockIdx.x;              // 0..4095
    int b = row >> 10;
    int e4 = threadIdx.x;              // 0..127 (float4 lane)
    float lut0 = g_lut[0];
    float4 us = ((const float4*)g_usum)[b * 128 + e4];
    float4 acc = make_float4(us.x * lut0, us.y * lut0, us.z * lut0, us.w * lut0);
    int n = g_nzc[row];
    const int* oi = g_nzi + (size_t)row * LL;
    const float* ow = g_nzw + (size_t)row * LL;
    const float4* ub = (const float4*)g_u + (size_t)b * LL * 128;
    for (int t = 0; t < n; t++) {
        int j = oi[t];
        float w = ow[t];
        float4 u4 = ub[(size_t)j * 128 + e4];
        acc.x += w * u4.x; acc.y += w * u4.y;
        acc.z += w * u4.z; acc.w += w * u4.w;
    }
    float inv = g_rowinv[row];
    float4 cc = ((const float4*)g_cvec)[e4];
    float4 o = make_float4(acc.x * inv + cc.x, acc.y * inv + cc.y,
                           acc.z * inv + cc.z, acc.w * inv + cc.w);
    ((float4*)out)[(size_t)row * 128 + e4] = o;
}

// ---------------- launch ----------------
extern "C" void kernel_launch(void* const* d_in, const int* in_sizes, int n_in,
                              void* d_out, int out_size) {
    // input order: query,key,value,token_sets_q,token_sets_k,hash_a,hash_b,
    //              Wq,bq,Wk,bk,Wv,bv,Wo,bo
    const float* value = (const float*)d_in[2];
    const void*  tsq   = d_in[3];
    const void*  tsk   = d_in[4];
    const void*  ha    = d_in[5];
    const void*  hb    = d_in[6];
    const float* Wv    = (const float*)d_in[11];
    const float* bv    = (const float*)d_in[12];
    const float* Wo    = (const float*)d_in[13];
    const float* bo    = (const float*)d_in[14];
    float* out = (float*)d_out;

    init_kernel<<<1, 160>>>(ha);
    sketch_kernel<<<2 * BZ * LL, 128>>>(tsq, tsk, ha, hb);
    transpose_kernel<<<dim3(16, 16), dim3(32, 8)>>>(Wv);
    gemm_M2_kernel<<<dim3(EE / 128, EE / 64), 256>>>(Wo);
    gemm_u_kernel<<<dim3(BZ * LL / 128, EE / 64), 256>>>(value);
    usum_kernel<<<dim3(EE / 128, BZ), 128>>>();
    cvec_kernel<<<EE / 128, 128>>>(Wo, bv, bo);
    count_kernel<<<dim3(LL / 64, LL / 64, BZ), 256>>>();
    build_sparse_kernel<<<BZ * LL / 8, 256>>>();
    out_kernel<<<BZ * LL, 128>>>(out);
}